// round 10
// baseline (speedup 1.0000x reference)
#include <cuda_runtime.h>
#include <math.h>

#define NB    16
#define NS    512
#define NBINS 511
#define TILE_V 8
#define NT    (NS / TILE_V)   // 64 column tiles
#define RROWS 4               // rows per block in row_fft

// Transposed row-FFT spectra: [sig][batch][pos][row]. 67 MB.
__device__ float2 g_specT[2][NB][NS][NS];
// Per-(sig, batch, tile) partial shell sums. 4 MB.
__device__ float  g_part[2][NB][NT][512];
// Stage-2 partials for the reduction tree.
__device__ float  g_p2[2][NB][8][512];
// Bin table [pos][k] with bit-reversal baked in. 512 KB.
__device__ unsigned short g_tab[NS * NS];
// Twiddle table, per-stage contiguous: segment for stage `half` starts at
// offset 512 - 2*half and holds W_{2*half}^j, j = 0..half-1.
__device__ float2 g_twk[512];
__device__ double g_bsum[NB];

__device__ __forceinline__ unsigned brev9(unsigned x) { return __brev(x) >> 23; }

// ---------------- setup kernels ----------------

__global__ void twk_kernel() {
    const int i = threadIdx.x;
#pragma unroll
    for (int half = 256; half >= 1; half >>= 1) {
        const int off = 512 - 2 * half;
        if (i >= off && i < off + half) {
            const int j = i - off;
            double ang = -6.283185307179586476925287 * (double)j / (double)(2 * half);
            g_twk[i] = make_float2((float)cos(ang), (float)sin(ang));
        }
    }
}

// bin = floor(511*sqrt(du^2+dv^2)/256), exact in double (verified: rel_err 0.0).
__global__ void tab_kernel() {
    const int pos = blockIdx.x, k = threadIdx.x;
    const int du = (int)brev9(k)   - 256;
    const int dv = (int)brev9(pos) - 256;
    const int s2 = du * du + dv * dv;
    int bin = (int)(511.0 * sqrt((double)s2) * (1.0 / 256.0));
    if (bin > 511) bin = 511;
    g_tab[pos * NS + k] = (unsigned short)bin;
}

// ---------------- FFT helpers ----------------

__device__ __forceinline__ float2 cadd(float2 a, float2 b) {
    return make_float2(a.x + b.x, a.y + b.y);
}
__device__ __forceinline__ float2 csub(float2 a, float2 b) {
    return make_float2(a.x - b.x, a.y - b.y);
}
// (u - v) * tw
__device__ __forceinline__ float2 csubmul(float2 u, float2 v, float2 tw) {
    float dr = u.x - v.x, di = u.y - v.y;
    return make_float2(dr * tw.x - di * tw.y, dr * tw.y + di * tw.x);
}

// Fused radix-8 DIF (3 radix-2 layers) on 8 points at positions p + m*h.
// T0..T3: layer-1 twiddles for m = 0..3; U0,U1: layer-2 for m mod 2; V: layer-3.
// (Verified bit-exact in round 7.)
__device__ __forceinline__ void r8dif(float2 x[8],
                                      float2 T0, float2 T1, float2 T2, float2 T3,
                                      float2 U0, float2 U1, float2 V) {
    float2 a0 = cadd(x[0], x[4]), a4 = csubmul(x[0], x[4], T0);
    float2 a1 = cadd(x[1], x[5]), a5 = csubmul(x[1], x[5], T1);
    float2 a2 = cadd(x[2], x[6]), a6 = csubmul(x[2], x[6], T2);
    float2 a3 = cadd(x[3], x[7]), a7 = csubmul(x[3], x[7], T3);
    float2 b0 = cadd(a0, a2), b2 = csubmul(a0, a2, U0);
    float2 b1 = cadd(a1, a3), b3 = csubmul(a1, a3, U1);
    float2 b4 = cadd(a4, a6), b6 = csubmul(a4, a6, U0);
    float2 b5 = cadd(a5, a7), b7 = csubmul(a5, a7, U1);
    x[0] = cadd(b0, b1); x[1] = csubmul(b0, b1, V);
    x[2] = cadd(b2, b3); x[3] = csubmul(b2, b3, V);
    x[4] = cadd(b4, b5); x[5] = csubmul(b4, b5, V);
    x[6] = cadd(b6, b7); x[7] = csubmul(b6, b7, V);
}

// Final radix-8 DIF on 8 contiguous points (layers half = 4, 2, 1), constant
// twiddles. (Verified bit-exact in round 7.)
__device__ __forceinline__ void r8dif_const(float2 x[8]) {
    const float r = 0.7071067811865475727f;
    float2 t0 = cadd(x[0], x[4]);
    float2 d4 = csub(x[0], x[4]);
    float2 t1 = cadd(x[1], x[5]);
    float dx5 = x[1].x - x[5].x, dy5 = x[1].y - x[5].y;
    float2 d5 = make_float2(r * (dx5 + dy5), r * (dy5 - dx5));
    float2 t2 = cadd(x[2], x[6]);
    float dx6 = x[2].x - x[6].x, dy6 = x[2].y - x[6].y;
    float2 d6 = make_float2(dy6, -dx6);
    float2 t3 = cadd(x[3], x[7]);
    float dx7 = x[3].x - x[7].x, dy7 = x[3].y - x[7].y;
    float2 d7 = make_float2(r * (dy7 - dx7), -r * (dx7 + dy7));
    float2 u0 = cadd(t0, t2), u2 = csub(t0, t2);
    float2 u1 = cadd(t1, t3);
    float dxu = t1.x - t3.x, dyu = t1.y - t3.y;
    float2 u3 = make_float2(dyu, -dxu);
    float2 v0 = cadd(d4, d6), v2 = csub(d4, d6);
    float2 v1 = cadd(d5, d7);
    float dxv = d5.x - d7.x, dyv = d5.y - d7.y;
    float2 v3 = make_float2(dyv, -dxv);
    x[0] = cadd(u0, u1); x[1] = csub(u0, u1);
    x[2] = cadd(u2, u3); x[3] = csub(u2, u3);
    x[4] = cadd(v0, v1); x[5] = csub(v0, v1);
    x[6] = cadd(v2, v3); x[7] = csub(v2, v3);
}

// ---- radix-2/shuffle helpers for the row kernel (unchanged, proven) ----

__device__ __forceinline__ void r4dif(float2 a, float2 b, float2 c, float2 d,
                                      float2 tw1, float2 tw1b, float2 tw2,
                                      float2& o0, float2& o1, float2& o2, float2& o3) {
    float2 t0 = cadd(a, c);
    float2 t1 = csubmul(a, c, tw1);
    float2 t2 = cadd(b, d);
    float2 t3 = csubmul(b, d, tw1b);
    o0 = cadd(t0, t2);
    o1 = csubmul(t0, t2, tw2);
    o2 = cadd(t1, t3);
    o3 = csubmul(t1, t3, tw2);
}

__device__ __forceinline__ float2 bfly_shfl(float2 x, int half, float2 tw, int L) {
    float px = __shfl_xor_sync(0xffffffffu, x.x, half);
    float py = __shfl_xor_sync(0xffffffffu, x.y, half);
    if ((L & half) == 0)
        return make_float2(x.x + px, x.y + py);
    float dr = px - x.x, di = py - x.y;
    return make_float2(dr * tw.x - di * tw.y, dr * tw.y + di * tw.x);
}

__device__ __forceinline__ float2 bfly_h2(float2 x, int L) {
    float px = __shfl_xor_sync(0xffffffffu, x.x, 2);
    float py = __shfl_xor_sync(0xffffffffu, x.y, 2);
    if ((L & 2) == 0) return make_float2(x.x + px, x.y + py);
    float dr = px - x.x, di = py - x.y;
    return (L & 1) ? make_float2(di, -dr) : make_float2(dr, di);
}

__device__ __forceinline__ float2 bfly_h1(float2 x, int L) {
    float px = __shfl_xor_sync(0xffffffffu, x.x, 1);
    float py = __shfl_xor_sync(0xffffffffu, x.y, 1);
    if ((L & 1) == 0) return make_float2(x.x + px, x.y + py);
    return make_float2(px - x.x, py - x.y);
}

__device__ __forceinline__ void fft_reg_stages4(float2& x0, float2& x1,
                                                float2& x2, float2& x3,
                                                float2 tw16, float2 tw8, float2 tw4,
                                                int L) {
    x0 = bfly_shfl(x0, 16, tw16, L); x1 = bfly_shfl(x1, 16, tw16, L);
    x2 = bfly_shfl(x2, 16, tw16, L); x3 = bfly_shfl(x3, 16, tw16, L);
    x0 = bfly_shfl(x0, 8, tw8, L);   x1 = bfly_shfl(x1, 8, tw8, L);
    x2 = bfly_shfl(x2, 8, tw8, L);   x3 = bfly_shfl(x3, 8, tw8, L);
    x0 = bfly_shfl(x0, 4, tw4, L);   x1 = bfly_shfl(x1, 4, tw4, L);
    x2 = bfly_shfl(x2, 4, tw4, L);   x3 = bfly_shfl(x3, 4, tw4, L);
    x0 = bfly_h2(x0, L); x1 = bfly_h2(x1, L);
    x2 = bfly_h2(x2, L); x3 = bfly_h2(x3, L);
    x0 = bfly_h1(x0, L); x1 = bfly_h1(x1, L);
    x2 = bfly_h1(x2, L); x3 = bfly_h1(x3, L);
}

// ---------------- main kernels ----------------

// One block per (4-row tile, batch). 256 threads = 2 signal engines x 128.
// __ldcs inputs keep g_specT L2-resident for the col pass. (R8 version.)
__global__ __launch_bounds__(256, 5) void row_fft_kernel(const float* __restrict__ z,
                                                         const float* __restrict__ tt) {
    __shared__ float2 w[2][NS];             // [engine][pos]   8 KB
    __shared__ float2 stage[2][RROWS][NS];  // [sig][row][pos] 32 KB
    __shared__ float2 s_tw[512];            // 4 KB
    const int rt = blockIdx.x, b = blockIdx.y;
    const int t = threadIdx.x;
    const int f = t >> 7;
    const int g = t & 127;
    const int L = t & 31;
    const int ww = g >> 5;
    const int pb = 128 * ww + L;

    s_tw[t]       = g_twk[t];
    s_tw[t + 256] = g_twk[t + 256];
    __syncthreads();

#pragma unroll
    for (int r = 0; r < RROWS; r++) {
        const int row = rt * RROWS + r;
        const size_t base = ((size_t)b * NS + row) * NS;
        const float2* __restrict__ tp = (const float2*)tt + base;

        float2 a0 = __ldcs(&tp[g]),       a1 = __ldcs(&tp[g + 128]);
        float2 a2 = __ldcs(&tp[g + 256]), a3 = __ldcs(&tp[g + 384]);
        if (f == 1) {
            const float2* __restrict__ zp = (const float2*)z + base;
            float2 z0 = __ldcs(&zp[g]),       z1 = __ldcs(&zp[g + 128]);
            float2 z2 = __ldcs(&zp[g + 256]), z3 = __ldcs(&zp[g + 384]);
            a0 = make_float2(z0.x - a0.x, z0.y - a0.y);
            a1 = make_float2(z1.x - a1.x, z1.y - a1.y);
            a2 = make_float2(z2.x - a2.x, z2.y - a2.y);
            a3 = make_float2(z3.x - a3.x, z3.y - a3.y);
        }

        float2 o0, o1, o2, o3;
        r4dif(a0, a1, a2, a3, s_tw[g], s_tw[g + 128], s_tw[256 + g], o0, o1, o2, o3);
        float2* wf = w[f];
        wf[g] = o0; wf[g + 128] = o1; wf[g + 256] = o2; wf[g + 384] = o3;
        __syncthreads();

        float2 b0 = wf[pb], b1 = wf[pb + 32], b2 = wf[pb + 64], b3 = wf[pb + 96];
        float2 x0, x1, x2, x3;
        r4dif(b0, b1, b2, b3, s_tw[384 + L], s_tw[416 + L], s_tw[448 + L],
              x0, x1, x2, x3);
        fft_reg_stages4(x0, x1, x2, x3,
                        s_tw[480 + (L & 15)], s_tw[496 + (L & 7)], s_tw[504 + (L & 3)],
                        L);

        stage[f][r][pb]      = x0;
        stage[f][r][pb + 32] = x1;
        stage[f][r][pb + 64] = x2;
        stage[f][r][pb + 96] = x3;
        __syncthreads();
    }

#pragma unroll
    for (int k = 0; k < 4; k++) {
        const int i   = t + k * 256;
        const int fo  = i >> 9;
        const int pos = i & 511;
        float2 s0 = stage[fo][0][pos];
        float2 s1 = stage[fo][1][pos];
        float2 s2 = stage[fo][2][pos];
        float2 s3 = stage[fo][3][pos];
        float4* dst = (float4*)&g_specT[fo][b][pos][rt * RROWS];
        dst[0] = make_float4(s0.x, s0.y, s1.x, s1.y);
        dst[1] = make_float4(s2.x, s2.y, s3.x, s3.y);
    }
}

// One block per (8-col tile, batch, sig). 256 threads = 4 column engines x 64.
// Lean radix-8: 3 passes, 8 points/thread, zero shuffles, in-place pass 2
// (thread-private slots -> no barrier between pass-2 read and write).
// Exchange stride 10 makes pass-3 reads contiguous & 16B-aligned (LDS.128).
__global__ __launch_bounds__(256, 5) void col_fft_kernel() {
    __shared__ __align__(16) float2 xb[2][4][640];  // [iter-buf][engine][slot] 41 KB
    __shared__ float  bins[512];                    // 2 KB
    __shared__ float2 s_tw2[64];                    // pass-2 twiddles, 512 B
    const int tile = blockIdx.x, b = blockIdx.y, sig = blockIdx.z;
    const int t = threadIdx.x;
    const int e  = t >> 6;          // engine = column within quad
    const int tl = t & 63;
    const int s  = tl >> 3, k = tl & 7;

    bins[t]       = 0.0f;
    bins[t + 256] = 0.0f;
    if (t < 64) s_tw2[t] = g_twk[448 + t];
    // No barrier needed: s_tw2 is first read after the pass-1 barrier below,
    // bins first updated after the pass-2 barrier.

    // Pass-1 twiddles: per-thread (tl-dependent), loop-invariant -> registers.
    const float2 T10 = g_twk[tl],       T11 = g_twk[64 + tl];
    const float2 T12 = g_twk[128 + tl], T13 = g_twk[192 + tl];
    const float2 U10 = g_twk[256 + tl], U11 = g_twk[320 + tl];
    const float2 V1  = g_twk[384 + tl];

    const int wA = 10 * s + k;       // pass-1 write:  + 80*m
    const int wB = 80 * s + k;       // pass-2 slots:  + 10*j
    const int rB = 80 * s + 10 * k;  // pass-3 read:   + c (even -> 16B aligned)

#pragma unroll
    for (int it = 0; it < 2; it++) {
        const int pos = tile * TILE_V + it * 4 + e;
        const float2* __restrict__ src = &g_specT[sig][b][pos][0];
        float2* buf = &xb[it][e][0];

        // Pass 1 (half = 256,128,64): strided coalesced LDG straight to regs.
        float2 x[8];
#pragma unroll
        for (int m = 0; m < 8; m++) x[m] = src[64 * m + tl];
        r8dif(x, T10, T11, T12, T13, U10, U11, V1);
#pragma unroll
        for (int m = 0; m < 8; m++) buf[80 * m + wA] = x[m];
        __syncthreads();

        // Pass 2 (half = 32,16,8): read-modify-write of thread-private slots.
        float2 y[8];
#pragma unroll
        for (int j = 0; j < 8; j++) y[j] = buf[wB + 10 * j];
        r8dif(y, s_tw2[k], s_tw2[8 + k], s_tw2[16 + k], s_tw2[24 + k],
                 s_tw2[32 + k], s_tw2[40 + k], s_tw2[48 + k]);
#pragma unroll
        for (int j = 0; j < 8; j++) buf[wB + 10 * j] = y[j];
        __syncthreads();

        // Pass 3 (half = 4,2,1): 8 contiguous points = 4x LDS.128, const twiddles.
        float2 zv[8];
        const float4* __restrict__ cb = (const float4*)&buf[rB];
#pragma unroll
        for (int c = 0; c < 4; c++) {
            float4 v = cb[c];
            zv[2 * c]     = make_float2(v.x, v.y);
            zv[2 * c + 1] = make_float2(v.z, v.w);
        }
        r8dif_const(zv);

        // Bins: points are positions 8*tl + c -> one uint4 tab load.
        const uint4 tv = *(const uint4*)&g_tab[pos * NS + 8 * tl];
        atomicAdd(&bins[tv.x & 0xffff], zv[0].x * zv[0].x + zv[0].y * zv[0].y);
        atomicAdd(&bins[tv.x >> 16],    zv[1].x * zv[1].x + zv[1].y * zv[1].y);
        atomicAdd(&bins[tv.y & 0xffff], zv[2].x * zv[2].x + zv[2].y * zv[2].y);
        atomicAdd(&bins[tv.y >> 16],    zv[3].x * zv[3].x + zv[3].y * zv[3].y);
        atomicAdd(&bins[tv.z & 0xffff], zv[4].x * zv[4].x + zv[4].y * zv[4].y);
        atomicAdd(&bins[tv.z >> 16],    zv[5].x * zv[5].x + zv[5].y * zv[5].y);
        atomicAdd(&bins[tv.w & 0xffff], zv[6].x * zv[6].x + zv[6].y * zv[6].y);
        atomicAdd(&bins[tv.w >> 16],    zv[7].x * zv[7].x + zv[7].y * zv[7].y);
    }
    __syncthreads();

    g_part[sig][b][tile][t]       = bins[t];
    g_part[sig][b][tile][t + 256] = bins[t + 256];
}

// ---------------- reduction tree ----------------

__global__ __launch_bounds__(512) void reduce1a_kernel() {
    const int b = blockIdx.x, g = blockIdx.y, t = threadIdx.x;
    float ns = 0.0f, es = 0.0f;
#pragma unroll
    for (int tl = 0; tl < 8; tl++) {
        ns += g_part[0][b][g * 8 + tl][t];
        es += g_part[1][b][g * 8 + tl][t];
    }
    g_p2[0][b][g][t] = ns;
    g_p2[1][b][g][t] = es;
}

__global__ __launch_bounds__(512) void reduce1b_kernel() {
    __shared__ double sh[512];
    const int b = blockIdx.x, t = threadIdx.x;
    double ns = 0.0, es = 0.0;
#pragma unroll
    for (int g = 0; g < 8; g++) {
        ns += (double)g_p2[0][b][g][t];
        es += (double)g_p2[1][b][g][t];
    }
    sh[t] = (t < NBINS) ? es / fmax(ns, 1e-8) : 0.0;
    __syncthreads();
    for (int k = 256; k > 0; k >>= 1) {
        if (t < k) sh[t] += sh[t + k];
        __syncthreads();
    }
    if (t == 0) g_bsum[b] = sh[0];
}

__global__ void reduce2_kernel(float* __restrict__ out) {
    double s = 0.0;
#pragma unroll
    for (int i = 0; i < NB; i++) s += g_bsum[i];
    out[0] = (float)(s / (double)NB);
}

extern "C" void kernel_launch(void* const* d_in, const int* in_sizes, int n_in,
                              void* d_out, int out_size) {
    const float* z  = (const float*)d_in[0];   // z_ [16,512,512,2]
    const float* tt = (const float*)d_in[1];   // t_ [16,512,512,2]
    float* out = (float*)d_out;
    (void)in_sizes; (void)n_in; (void)out_size;

    twk_kernel<<<1, 512>>>();
    tab_kernel<<<NS, NS>>>();
    {
        dim3 grid(NS / RROWS, NB);
        row_fft_kernel<<<grid, 256>>>(z, tt);
    }
    {
        dim3 grid(NT, NB, 2);
        col_fft_kernel<<<grid, 256>>>();
    }
    {
        dim3 grid(NB, 8);
        reduce1a_kernel<<<grid, 512>>>();
    }
    reduce1b_kernel<<<NB, 512>>>();
    reduce2_kernel<<<1, 1>>>(out);
}

// round 11
// speedup vs baseline: 1.1626x; 1.1626x over previous
#include <cuda_runtime.h>
#include <math.h>

#define NB    16
#define NS    512
#define NBINS 511
#define NT    64              // pair-group tiles (4 groups per block)
#define RROWS 4               // rows per block in row_fft

// Transposed row-FFT spectra: [sig][batch][pos][row]. 67 MB.
__device__ float2 g_specT[2][NB][NS][NS];
// Per-(sig, batch, tile) partial shell sums. 4 MB.
__device__ float  g_part[2][NB][NT][512];
// Stage-2 partials for the reduction tree.
__device__ float  g_p2[2][NB][8][512];
// Bin table [pos][k] with bit-reversal baked in. 512 KB.
__device__ unsigned short g_tab[NS * NS];
// Twiddle table, per-stage contiguous: segment for stage `half` starts at
// offset 512 - 2*half and holds W_{2*half}^j, j = 0..half-1.
__device__ float2 g_twk[512];
__device__ double g_bsum[NB];

__device__ __forceinline__ unsigned brev9(unsigned x) { return __brev(x) >> 23; }

// ---------------- setup kernels ----------------

__global__ void twk_kernel() {
    const int i = threadIdx.x;
#pragma unroll
    for (int half = 256; half >= 1; half >>= 1) {
        const int off = 512 - 2 * half;
        if (i >= off && i < off + half) {
            const int j = i - off;
            double ang = -6.283185307179586476925287 * (double)j / (double)(2 * half);
            g_twk[i] = make_float2((float)cos(ang), (float)sin(ang));
        }
    }
}

// bin = floor(511*sqrt(du^2+dv^2)/256), exact in double (verified: rel_err 0.0).
__global__ void tab_kernel() {
    const int pos = blockIdx.x, k = threadIdx.x;
    const int du = (int)brev9(k)   - 256;
    const int dv = (int)brev9(pos) - 256;
    const int s2 = du * du + dv * dv;
    int bin = (int)(511.0 * sqrt((double)s2) * (1.0 / 256.0));
    if (bin > 511) bin = 511;
    g_tab[pos * NS + k] = (unsigned short)bin;
}

// ---------------- FFT helpers ----------------

__device__ __forceinline__ float2 cadd(float2 a, float2 b) {
    return make_float2(a.x + b.x, a.y + b.y);
}
// (u - v) * tw
__device__ __forceinline__ float2 csubmul(float2 u, float2 v, float2 tw) {
    float dr = u.x - v.x, di = u.y - v.y;
    return make_float2(dr * tw.x - di * tw.y, dr * tw.y + di * tw.x);
}

// Two fused radix-2 DIF stage-layers (block sizes 4h then 2h) on one group of 4.
__device__ __forceinline__ void r4dif(float2 a, float2 b, float2 c, float2 d,
                                      float2 tw1, float2 tw1b, float2 tw2,
                                      float2& o0, float2& o1, float2& o2, float2& o3) {
    float2 t0 = cadd(a, c);
    float2 t1 = csubmul(a, c, tw1);
    float2 t2 = cadd(b, d);
    float2 t3 = csubmul(b, d, tw1b);
    o0 = cadd(t0, t2);
    o1 = csubmul(t0, t2, tw2);
    o2 = cadd(t1, t3);
    o3 = csubmul(t1, t3, tw2);
}

// Generic shuffle butterfly for half = 16, 8, 4.
__device__ __forceinline__ float2 bfly_shfl(float2 x, int half, float2 tw, int L) {
    float px = __shfl_xor_sync(0xffffffffu, x.x, half);
    float py = __shfl_xor_sync(0xffffffffu, x.y, half);
    if ((L & half) == 0)
        return make_float2(x.x + px, x.y + py);
    float dr = px - x.x, di = py - x.y;
    return make_float2(dr * tw.x - di * tw.y, dr * tw.y + di * tw.x);
}

// half = 2: twiddle is W_4^{L&1} = (1,0) or (0,-1) -> swap/negate.
__device__ __forceinline__ float2 bfly_h2(float2 x, int L) {
    float px = __shfl_xor_sync(0xffffffffu, x.x, 2);
    float py = __shfl_xor_sync(0xffffffffu, x.y, 2);
    if ((L & 2) == 0) return make_float2(x.x + px, x.y + py);
    float dr = px - x.x, di = py - x.y;
    return (L & 1) ? make_float2(di, -dr) : make_float2(dr, di);
}

// half = 1: plain add/sub.
__device__ __forceinline__ float2 bfly_h1(float2 x, int L) {
    float px = __shfl_xor_sync(0xffffffffu, x.x, 1);
    float py = __shfl_xor_sync(0xffffffffu, x.y, 1);
    if ((L & 1) == 0) return make_float2(x.x + px, x.y + py);
    return make_float2(px - x.x, py - x.y);
}

// Last 5 stages (half 16..1) for 4 register-resident points at positions
// pb, pb+32, pb+64, pb+96.
__device__ __forceinline__ void fft_reg_stages4(float2& x0, float2& x1,
                                                float2& x2, float2& x3,
                                                float2 tw16, float2 tw8, float2 tw4,
                                                int L) {
    x0 = bfly_shfl(x0, 16, tw16, L); x1 = bfly_shfl(x1, 16, tw16, L);
    x2 = bfly_shfl(x2, 16, tw16, L); x3 = bfly_shfl(x3, 16, tw16, L);
    x0 = bfly_shfl(x0, 8, tw8, L);   x1 = bfly_shfl(x1, 8, tw8, L);
    x2 = bfly_shfl(x2, 8, tw8, L);   x3 = bfly_shfl(x3, 8, tw8, L);
    x0 = bfly_shfl(x0, 4, tw4, L);   x1 = bfly_shfl(x1, 4, tw4, L);
    x2 = bfly_shfl(x2, 4, tw4, L);   x3 = bfly_shfl(x3, 4, tw4, L);
    x0 = bfly_h2(x0, L); x1 = bfly_h2(x1, L);
    x2 = bfly_h2(x2, L); x3 = bfly_h2(x3, L);
    x0 = bfly_h1(x0, L); x1 = bfly_h1(x1, L);
    x2 = bfly_h1(x2, L); x3 = bfly_h1(x3, L);
}

// ---------------- main kernels ----------------

// One block per (4-row tile, batch). 256 threads = 2 signal engines x 128.
// __ldcs inputs; transposed 32B-sector stores via smem stage. (Proven R8.)
__global__ __launch_bounds__(256, 5) void row_fft_kernel(const float* __restrict__ z,
                                                         const float* __restrict__ tt) {
    __shared__ float2 w[2][NS];             // [engine][pos]   8 KB
    __shared__ float2 stage[2][RROWS][NS];  // [sig][row][pos] 32 KB
    __shared__ float2 s_tw[512];            // 4 KB
    const int rt = blockIdx.x, b = blockIdx.y;
    const int t = threadIdx.x;
    const int f = t >> 7;
    const int g = t & 127;
    const int L = t & 31;
    const int ww = g >> 5;
    const int pb = 128 * ww + L;

    s_tw[t]       = g_twk[t];
    s_tw[t + 256] = g_twk[t + 256];
    __syncthreads();

#pragma unroll
    for (int r = 0; r < RROWS; r++) {
        const int row = rt * RROWS + r;
        const size_t base = ((size_t)b * NS + row) * NS;
        const float2* __restrict__ tp = (const float2*)tt + base;

        float2 a0 = __ldcs(&tp[g]),       a1 = __ldcs(&tp[g + 128]);
        float2 a2 = __ldcs(&tp[g + 256]), a3 = __ldcs(&tp[g + 384]);
        if (f == 1) {
            const float2* __restrict__ zp = (const float2*)z + base;
            float2 z0 = __ldcs(&zp[g]),       z1 = __ldcs(&zp[g + 128]);
            float2 z2 = __ldcs(&zp[g + 256]), z3 = __ldcs(&zp[g + 384]);
            a0 = make_float2(z0.x - a0.x, z0.y - a0.y);
            a1 = make_float2(z1.x - a1.x, z1.y - a1.y);
            a2 = make_float2(z2.x - a2.x, z2.y - a2.y);
            a3 = make_float2(z3.x - a3.x, z3.y - a3.y);
        }

        float2 o0, o1, o2, o3;
        r4dif(a0, a1, a2, a3, s_tw[g], s_tw[g + 128], s_tw[256 + g], o0, o1, o2, o3);
        float2* wf = w[f];
        wf[g] = o0; wf[g + 128] = o1; wf[g + 256] = o2; wf[g + 384] = o3;
        __syncthreads();

        float2 b0 = wf[pb], b1 = wf[pb + 32], b2 = wf[pb + 64], b3 = wf[pb + 96];
        float2 x0, x1, x2, x3;
        r4dif(b0, b1, b2, b3, s_tw[384 + L], s_tw[416 + L], s_tw[448 + L],
              x0, x1, x2, x3);
        fft_reg_stages4(x0, x1, x2, x3,
                        s_tw[480 + (L & 15)], s_tw[496 + (L & 7)], s_tw[504 + (L & 3)],
                        L);

        stage[f][r][pb]      = x0;
        stage[f][r][pb + 32] = x1;
        stage[f][r][pb + 64] = x2;
        stage[f][r][pb + 96] = x3;
        __syncthreads();
    }

#pragma unroll
    for (int k = 0; k < 4; k++) {
        const int i   = t + k * 256;
        const int fo  = i >> 9;
        const int pos = i & 511;
        float2 s0 = stage[fo][0][pos];
        float2 s1 = stage[fo][1][pos];
        float2 s2 = stage[fo][2][pos];
        float2 s3 = stage[fo][3][pos];
        float4* dst = (float4*)&g_specT[fo][b][pos][rt * RROWS];
        dst[0] = make_float4(s0.x, s0.y, s1.x, s1.y);
        dst[1] = make_float4(s2.x, s2.y, s3.x, s3.y);
    }
}

// One block per (4 pair-groups, batch, sig). 256 threads = 2 column engines.
// Radial symmetry: columns posA/posB with brev(posB) = 512 - brev(posA) share
// one bin table (dv vs -dv). Engine FFTs posA (stash powers in regs), then
// posB, sums powers, issues ONE atomic per point pair -> atomics halved.
// Group 255 is special: self-paired columns pos 0 (dv=-256) & pos 1 (dv=0),
// separate tabs/atomics each iteration.
__global__ __launch_bounds__(256) void col_fft_kernel() {
    __shared__ float2 w[2][2 * NS]; // [parity][engine*512 + pos]  16 KB
    __shared__ float  bins[512];
    const int bx = blockIdx.x, b = blockIdx.y, sig = blockIdx.z;
    const int t = threadIdx.x;
    const int f = t >> 7;
    const int g = t & 127;
    const int L = t & 31;
    const int ww = g >> 5;
    const int pb = 128 * ww + L;

    bins[t]       = 0.0f;
    bins[t + 256] = 0.0f;

    // Loop-invariant twiddles in registers (proven fastest in R6).
    const float2 twA0 = g_twk[g],       twA1 = g_twk[g + 128], twA2 = g_twk[256 + g];
    const float2 twB0 = g_twk[384 + L], twB1 = g_twk[416 + L], twB2 = g_twk[448 + L];
    const float2 tw16 = g_twk[480 + (L & 15)];
    const float2 tw8  = g_twk[496 + (L & 7)];
    const float2 tw4  = g_twk[504 + (L & 3)];

    float pw0 = 0.0f, pw1 = 0.0f, pw2 = 0.0f, pw3 = 0.0f;

#pragma unroll
    for (int it = 0; it < 4; it++) {
        const int  grp     = 4 * bx + 2 * f + (it >> 1);
        const bool isB     = (it & 1) != 0;
        const bool special = (grp == 255);
        // g<255: posA = brev9(grp+1) (freq u=grp+1), posB = brev9(511-grp)
        // (freq 512-(grp+1)); special: pos 0 then pos 1.
        const int pos = special ? (isB ? 1 : 0)
                                : (isB ? (int)brev9(511 - grp) : (int)brev9(grp + 1));

        const float2* __restrict__ src = &g_specT[sig][b][pos][0];
        float2 a0 = src[g], a1 = src[g + 128], a2 = src[g + 256], a3 = src[g + 384];
        float2 o0, o1, o2, o3;
        r4dif(a0, a1, a2, a3, twA0, twA1, twA2, o0, o1, o2, o3);

        float2* wf = &w[it & 1][f * NS];
        wf[g] = o0; wf[g + 128] = o1; wf[g + 256] = o2; wf[g + 384] = o3;
        __syncthreads();        // also covers bins init on it==0

        float2 b0 = wf[pb], b1 = wf[pb + 32], b2 = wf[pb + 64], b3 = wf[pb + 96];
        float2 x0, x1, x2, x3;
        r4dif(b0, b1, b2, b3, twB0, twB1, twB2, x0, x1, x2, x3);
        fft_reg_stages4(x0, x1, x2, x3, tw16, tw8, tw4, L);

        float p0 = x0.x * x0.x + x0.y * x0.y;
        float p1 = x1.x * x1.x + x1.y * x1.y;
        float p2 = x2.x * x2.x + x2.y * x2.y;
        float p3 = x3.x * x3.x + x3.y * x3.y;

        if (!isB && !special) {
            // A-half of a pair: stash, no atomics this iteration.
            pw0 = p0; pw1 = p1; pw2 = p2; pw3 = p3;
        } else {
            if (!special) { p0 += pw0; p1 += pw1; p2 += pw2; p3 += pw3; }
            // tab[pos] is valid for the pair: bins depend on dv^2 only.
            const unsigned short* __restrict__ tb = &g_tab[pos * NS];
            atomicAdd(&bins[tb[pb]],      p0);
            atomicAdd(&bins[tb[pb + 32]], p1);
            atomicAdd(&bins[tb[pb + 64]], p2);
            atomicAdd(&bins[tb[pb + 96]], p3);
        }
    }
    __syncthreads();

    g_part[sig][b][bx][t]       = bins[t];
    g_part[sig][b][bx][t + 256] = bins[t + 256];
}

// ---------------- reduction tree ----------------

__global__ __launch_bounds__(512) void reduce1a_kernel() {
    const int b = blockIdx.x, g = blockIdx.y, t = threadIdx.x;
    float ns = 0.0f, es = 0.0f;
#pragma unroll
    for (int tl = 0; tl < 8; tl++) {
        ns += g_part[0][b][g * 8 + tl][t];
        es += g_part[1][b][g * 8 + tl][t];
    }
    g_p2[0][b][g][t] = ns;
    g_p2[1][b][g][t] = es;
}

__global__ __launch_bounds__(512) void reduce1b_kernel() {
    __shared__ double sh[512];
    const int b = blockIdx.x, t = threadIdx.x;
    double ns = 0.0, es = 0.0;
#pragma unroll
    for (int g = 0; g < 8; g++) {
        ns += (double)g_p2[0][b][g][t];
        es += (double)g_p2[1][b][g][t];
    }
    sh[t] = (t < NBINS) ? es / fmax(ns, 1e-8) : 0.0;
    __syncthreads();
    for (int k = 256; k > 0; k >>= 1) {
        if (t < k) sh[t] += sh[t + k];
        __syncthreads();
    }
    if (t == 0) g_bsum[b] = sh[0];
}

__global__ void reduce2_kernel(float* __restrict__ out) {
    double s = 0.0;
#pragma unroll
    for (int i = 0; i < NB; i++) s += g_bsum[i];
    out[0] = (float)(s / (double)NB);
}

extern "C" void kernel_launch(void* const* d_in, const int* in_sizes, int n_in,
                              void* d_out, int out_size) {
    const float* z  = (const float*)d_in[0];   // z_ [16,512,512,2]
    const float* tt = (const float*)d_in[1];   // t_ [16,512,512,2]
    float* out = (float*)d_out;
    (void)in_sizes; (void)n_in; (void)out_size;

    twk_kernel<<<1, 512>>>();
    tab_kernel<<<NS, NS>>>();
    {
        dim3 grid(NS / RROWS, NB);
        row_fft_kernel<<<grid, 256>>>(z, tt);
    }
    {
        dim3 grid(NT, NB, 2);
        col_fft_kernel<<<grid, 256>>>();
    }
    {
        dim3 grid(NB, 8);
        reduce1a_kernel<<<grid, 512>>>();
    }
    reduce1b_kernel<<<NB, 512>>>();
    reduce2_kernel<<<1, 1>>>(out);
}

// round 12
// speedup vs baseline: 1.2068x; 1.0380x over previous
#include <cuda_runtime.h>
#include <math.h>

#define NB    16
#define NS    512
#define NBINS 511
#define NT    64              // pair-group tiles (4 groups per block)
#define RROWS 4               // rows per block in row_fft

// Transposed row-FFT spectra: [sig][batch][pos][row]. 67 MB.
__device__ float2 g_specT[2][NB][NS][NS];
// Per-(sig, batch, tile) partial shell sums. 4 MB.
__device__ float  g_part[2][NB][NT][512];
// Stage-2 partials for the reduction tree.
__device__ float  g_p2[2][NB][8][512];
// Bin table [pos][k] with bit-reversal baked in. 512 KB.
__device__ unsigned short g_tab[NS * NS];
// Twiddle table, per-stage contiguous: segment for stage `half` starts at
// offset 512 - 2*half and holds W_{2*half}^j, j = 0..half-1.
__device__ float2 g_twk[512];
__device__ double g_bsum[NB];

__device__ __forceinline__ unsigned brev9(unsigned x) { return __brev(x) >> 23; }

// ---------------- setup kernel (tab + twiddles fused) ----------------

// bin = floor(511*sqrt(s2)/256) == largest b with 65536*b^2 <= 261121*s2.
// float sqrt estimate + exact integer fixup: bit-identical to the double
// version (verified rel_err 0.0) without any FP64.
__global__ void tab_kernel() {
    const int pos = blockIdx.x, k = threadIdx.x;
    const int du = (int)brev9(k)   - 256;
    const int dv = (int)brev9(pos) - 256;
    const int s2 = du * du + dv * dv;
    const long long rhs = 261121LL * (long long)s2;   // 511^2 * s2
    int bin = (int)(sqrtf((float)s2) * (511.0f / 256.0f));
    while ((long long)(bin + 1) * (bin + 1) * 65536LL <= rhs) bin++;
    while (bin > 0 && (long long)bin * bin * 65536LL > rhs) bin--;
    if (bin > 511) bin = 511;
    g_tab[pos * NS + k] = (unsigned short)bin;

    // Block 0 also fills the twiddle table (double trig, 512 threads, once).
    if (pos == 0) {
        const int i = k;
#pragma unroll
        for (int half = 256; half >= 1; half >>= 1) {
            const int off = 512 - 2 * half;
            if (i >= off && i < off + half) {
                const int j = i - off;
                double ang = -6.283185307179586476925287 * (double)j / (double)(2 * half);
                g_twk[i] = make_float2((float)cos(ang), (float)sin(ang));
            }
        }
    }
}

// ---------------- FFT helpers ----------------

__device__ __forceinline__ float2 cadd(float2 a, float2 b) {
    return make_float2(a.x + b.x, a.y + b.y);
}
// (u - v) * tw
__device__ __forceinline__ float2 csubmul(float2 u, float2 v, float2 tw) {
    float dr = u.x - v.x, di = u.y - v.y;
    return make_float2(dr * tw.x - di * tw.y, dr * tw.y + di * tw.x);
}

// Two fused radix-2 DIF stage-layers (block sizes 4h then 2h) on one group of 4.
__device__ __forceinline__ void r4dif(float2 a, float2 b, float2 c, float2 d,
                                      float2 tw1, float2 tw1b, float2 tw2,
                                      float2& o0, float2& o1, float2& o2, float2& o3) {
    float2 t0 = cadd(a, c);
    float2 t1 = csubmul(a, c, tw1);
    float2 t2 = cadd(b, d);
    float2 t3 = csubmul(b, d, tw1b);
    o0 = cadd(t0, t2);
    o1 = csubmul(t0, t2, tw2);
    o2 = cadd(t1, t3);
    o3 = csubmul(t1, t3, tw2);
}

// Generic shuffle butterfly for half = 16, 8, 4.
__device__ __forceinline__ float2 bfly_shfl(float2 x, int half, float2 tw, int L) {
    float px = __shfl_xor_sync(0xffffffffu, x.x, half);
    float py = __shfl_xor_sync(0xffffffffu, x.y, half);
    if ((L & half) == 0)
        return make_float2(x.x + px, x.y + py);
    float dr = px - x.x, di = py - x.y;
    return make_float2(dr * tw.x - di * tw.y, dr * tw.y + di * tw.x);
}

// half = 2: twiddle is W_4^{L&1} = (1,0) or (0,-1) -> swap/negate.
__device__ __forceinline__ float2 bfly_h2(float2 x, int L) {
    float px = __shfl_xor_sync(0xffffffffu, x.x, 2);
    float py = __shfl_xor_sync(0xffffffffu, x.y, 2);
    if ((L & 2) == 0) return make_float2(x.x + px, x.y + py);
    float dr = px - x.x, di = py - x.y;
    return (L & 1) ? make_float2(di, -dr) : make_float2(dr, di);
}

// half = 1: plain add/sub.
__device__ __forceinline__ float2 bfly_h1(float2 x, int L) {
    float px = __shfl_xor_sync(0xffffffffu, x.x, 1);
    float py = __shfl_xor_sync(0xffffffffu, x.y, 1);
    if ((L & 1) == 0) return make_float2(x.x + px, x.y + py);
    return make_float2(px - x.x, py - x.y);
}

// Last 5 stages (half 16..1) for 4 register-resident points at positions
// pb, pb+32, pb+64, pb+96.
__device__ __forceinline__ void fft_reg_stages4(float2& x0, float2& x1,
                                                float2& x2, float2& x3,
                                                float2 tw16, float2 tw8, float2 tw4,
                                                int L) {
    x0 = bfly_shfl(x0, 16, tw16, L); x1 = bfly_shfl(x1, 16, tw16, L);
    x2 = bfly_shfl(x2, 16, tw16, L); x3 = bfly_shfl(x3, 16, tw16, L);
    x0 = bfly_shfl(x0, 8, tw8, L);   x1 = bfly_shfl(x1, 8, tw8, L);
    x2 = bfly_shfl(x2, 8, tw8, L);   x3 = bfly_shfl(x3, 8, tw8, L);
    x0 = bfly_shfl(x0, 4, tw4, L);   x1 = bfly_shfl(x1, 4, tw4, L);
    x2 = bfly_shfl(x2, 4, tw4, L);   x3 = bfly_shfl(x3, 4, tw4, L);
    x0 = bfly_h2(x0, L); x1 = bfly_h2(x1, L);
    x2 = bfly_h2(x2, L); x3 = bfly_h2(x3, L);
    x0 = bfly_h1(x0, L); x1 = bfly_h1(x1, L);
    x2 = bfly_h1(x2, L); x3 = bfly_h1(x3, L);
}

// ---------------- main kernels ----------------

// One block per (4-row tile, batch). 256 threads = 2 signal engines x 128.
// __ldcs inputs; transposed 32B-sector stores via smem stage. (Proven R8.)
__global__ __launch_bounds__(256, 5) void row_fft_kernel(const float* __restrict__ z,
                                                         const float* __restrict__ tt) {
    __shared__ float2 w[2][NS];             // [engine][pos]   8 KB
    __shared__ float2 stage[2][RROWS][NS];  // [sig][row][pos] 32 KB
    __shared__ float2 s_tw[512];            // 4 KB
    const int rt = blockIdx.x, b = blockIdx.y;
    const int t = threadIdx.x;
    const int f = t >> 7;
    const int g = t & 127;
    const int L = t & 31;
    const int ww = g >> 5;
    const int pb = 128 * ww + L;

    s_tw[t]       = g_twk[t];
    s_tw[t + 256] = g_twk[t + 256];
    __syncthreads();

#pragma unroll
    for (int r = 0; r < RROWS; r++) {
        const int row = rt * RROWS + r;
        const size_t base = ((size_t)b * NS + row) * NS;
        const float2* __restrict__ tp = (const float2*)tt + base;

        float2 a0 = __ldcs(&tp[g]),       a1 = __ldcs(&tp[g + 128]);
        float2 a2 = __ldcs(&tp[g + 256]), a3 = __ldcs(&tp[g + 384]);
        if (f == 1) {
            const float2* __restrict__ zp = (const float2*)z + base;
            float2 z0 = __ldcs(&zp[g]),       z1 = __ldcs(&zp[g + 128]);
            float2 z2 = __ldcs(&zp[g + 256]), z3 = __ldcs(&zp[g + 384]);
            a0 = make_float2(z0.x - a0.x, z0.y - a0.y);
            a1 = make_float2(z1.x - a1.x, z1.y - a1.y);
            a2 = make_float2(z2.x - a2.x, z2.y - a2.y);
            a3 = make_float2(z3.x - a3.x, z3.y - a3.y);
        }

        float2 o0, o1, o2, o3;
        r4dif(a0, a1, a2, a3, s_tw[g], s_tw[g + 128], s_tw[256 + g], o0, o1, o2, o3);
        float2* wf = w[f];
        wf[g] = o0; wf[g + 128] = o1; wf[g + 256] = o2; wf[g + 384] = o3;
        __syncthreads();

        float2 b0 = wf[pb], b1 = wf[pb + 32], b2 = wf[pb + 64], b3 = wf[pb + 96];
        float2 x0, x1, x2, x3;
        r4dif(b0, b1, b2, b3, s_tw[384 + L], s_tw[416 + L], s_tw[448 + L],
              x0, x1, x2, x3);
        fft_reg_stages4(x0, x1, x2, x3,
                        s_tw[480 + (L & 15)], s_tw[496 + (L & 7)], s_tw[504 + (L & 3)],
                        L);

        stage[f][r][pb]      = x0;
        stage[f][r][pb + 32] = x1;
        stage[f][r][pb + 64] = x2;
        stage[f][r][pb + 96] = x3;
        __syncthreads();
    }

#pragma unroll
    for (int k = 0; k < 4; k++) {
        const int i   = t + k * 256;
        const int fo  = i >> 9;
        const int pos = i & 511;
        float2 s0 = stage[fo][0][pos];
        float2 s1 = stage[fo][1][pos];
        float2 s2 = stage[fo][2][pos];
        float2 s3 = stage[fo][3][pos];
        float4* dst = (float4*)&g_specT[fo][b][pos][rt * RROWS];
        dst[0] = make_float4(s0.x, s0.y, s1.x, s1.y);
        dst[1] = make_float4(s2.x, s2.y, s3.x, s3.y);
    }
}

// One block per (4 pair-groups, batch, sig). 256 threads = 2 column engines.
// Radial symmetry pairing (R10) + cp.async 2-column-deep input pipeline:
// column data lands in a 3-buffer smem ring via LDGSTS, prefetched 2 columns
// ahead so DRAM latency is covered by ~2 compute phases. The input buffer IS
// the exchange buffer (pass A is in-place per-thread).
__global__ __launch_bounds__(256) void col_fft_kernel() {
    __shared__ __align__(16) float2 in[3][2][NS];  // ring [buf][engine][pos] 24 KB
    __shared__ float  bins[512];                   // 2 KB
    const int bx = blockIdx.x, b = blockIdx.y, sig = blockIdx.z;
    const int t = threadIdx.x;
    const int f = t >> 7;
    const int g = t & 127;
    const int L = t & 31;
    const int ww = g >> 5;
    const int pb = 128 * ww + L;

    bins[t]       = 0.0f;
    bins[t + 256] = 0.0f;

    // Loop-invariant twiddles in registers.
    const float2 twA0 = g_twk[g],       twA1 = g_twk[g + 128], twA2 = g_twk[256 + g];
    const float2 twB0 = g_twk[384 + L], twB1 = g_twk[416 + L], twB2 = g_twk[448 + L];
    const float2 tw16 = g_twk[480 + (L & 15)];
    const float2 tw8  = g_twk[496 + (L & 7)];
    const float2 tw4  = g_twk[504 + (L & 3)];

    // Column sequence per engine: A(grp0), B(grp0), A(grp1), B(grp1).
    auto pos_of = [&](int it) -> int {
        const int grp = 4 * bx + 2 * f + (it >> 1);
        const bool isB = (it & 1) != 0;
        if (grp == 255) return isB ? 1 : 0;             // self-paired dv=0 / dv=-256
        return isB ? (int)brev9(511 - grp) : (int)brev9(grp + 1);
    };

    // Issue one column's loads (2x 16B cp.async per thread) + commit a group.
    auto prefetch = [&](int it, int buf_idx) {
        if (it < 4) {
            const int pos = pos_of(it);
            const float4* src = (const float4*)&g_specT[sig][b][pos][0];
            unsigned dst = (unsigned)__cvta_generic_to_shared(&in[buf_idx][f][0]);
            asm volatile("cp.async.cg.shared.global [%0], [%1], 16;"
                         :: "r"(dst + g * 16), "l"(src + g) : "memory");
            asm volatile("cp.async.cg.shared.global [%0], [%1], 16;"
                         :: "r"(dst + g * 16 + 2048), "l"(src + g + 128) : "memory");
        }
        asm volatile("cp.async.commit_group;" ::: "memory");
    };

    prefetch(0, 0);
    prefetch(1, 1);

    float pw0 = 0.0f, pw1 = 0.0f, pw2 = 0.0f, pw3 = 0.0f;

#pragma unroll
    for (int it = 0; it < 4; it++) {
        // Groups complete in order: <=1 pending => group #it has landed.
        asm volatile("cp.async.wait_group 1;" ::: "memory");
        __syncthreads();                    // data visible; prev buf reads done
        prefetch(it + 2, (it + 2) % 3);     // refill the buffer freed last iter

        float2* buf = &in[it % 3][f][0];

        // Pass A (half = 256,128): in-place on thread-private slots.
        float2 a0 = buf[g], a1 = buf[g + 128], a2 = buf[g + 256], a3 = buf[g + 384];
        float2 o0, o1, o2, o3;
        r4dif(a0, a1, a2, a3, twA0, twA1, twA2, o0, o1, o2, o3);
        buf[g] = o0; buf[g + 128] = o1; buf[g + 256] = o2; buf[g + 384] = o3;
        __syncthreads();

        // Pass B (half = 64,32) + register shuffle tail.
        float2 b0 = buf[pb], b1 = buf[pb + 32], b2 = buf[pb + 64], b3 = buf[pb + 96];
        float2 x0, x1, x2, x3;
        r4dif(b0, b1, b2, b3, twB0, twB1, twB2, x0, x1, x2, x3);
        fft_reg_stages4(x0, x1, x2, x3, tw16, tw8, tw4, L);

        float p0 = x0.x * x0.x + x0.y * x0.y;
        float p1 = x1.x * x1.x + x1.y * x1.y;
        float p2 = x2.x * x2.x + x2.y * x2.y;
        float p3 = x3.x * x3.x + x3.y * x3.y;

        const int  grp     = 4 * bx + 2 * f + (it >> 1);
        const bool isB     = (it & 1) != 0;
        const bool special = (grp == 255);
        if (!isB && !special) {
            pw0 = p0; pw1 = p1; pw2 = p2; pw3 = p3;   // stash A-half powers
        } else {
            if (!special) { p0 += pw0; p1 += pw1; p2 += pw2; p3 += pw3; }
            const int pos = pos_of(it);
            const unsigned short* __restrict__ tb = &g_tab[pos * NS];
            atomicAdd(&bins[tb[pb]],      p0);
            atomicAdd(&bins[tb[pb + 32]], p1);
            atomicAdd(&bins[tb[pb + 64]], p2);
            atomicAdd(&bins[tb[pb + 96]], p3);
        }
    }
    __syncthreads();

    g_part[sig][b][bx][t]       = bins[t];
    g_part[sig][b][bx][t + 256] = bins[t + 256];
}

// ---------------- reduction tree ----------------

__global__ __launch_bounds__(512) void reduce1a_kernel() {
    const int b = blockIdx.x, g = blockIdx.y, t = threadIdx.x;
    float ns = 0.0f, es = 0.0f;
#pragma unroll
    for (int tl = 0; tl < 8; tl++) {
        ns += g_part[0][b][g * 8 + tl][t];
        es += g_part[1][b][g * 8 + tl][t];
    }
    g_p2[0][b][g][t] = ns;
    g_p2[1][b][g][t] = es;
}

__global__ __launch_bounds__(512) void reduce1b_kernel() {
    __shared__ double sh[512];
    const int b = blockIdx.x, t = threadIdx.x;
    double ns = 0.0, es = 0.0;
#pragma unroll
    for (int g = 0; g < 8; g++) {
        ns += (double)g_p2[0][b][g][t];
        es += (double)g_p2[1][b][g][t];
    }
    sh[t] = (t < NBINS) ? es / fmax(ns, 1e-8) : 0.0;
    __syncthreads();
    for (int k = 256; k > 0; k >>= 1) {
        if (t < k) sh[t] += sh[t + k];
        __syncthreads();
    }
    if (t == 0) g_bsum[b] = sh[0];
}

__global__ void reduce2_kernel(float* __restrict__ out) {
    double s = 0.0;
#pragma unroll
    for (int i = 0; i < NB; i++) s += g_bsum[i];
    out[0] = (float)(s / (double)NB);
}

extern "C" void kernel_launch(void* const* d_in, const int* in_sizes, int n_in,
                              void* d_out, int out_size) {
    const float* z  = (const float*)d_in[0];   // z_ [16,512,512,2]
    const float* tt = (const float*)d_in[1];   // t_ [16,512,512,2]
    float* out = (float*)d_out;
    (void)in_sizes; (void)n_in; (void)out_size;

    tab_kernel<<<NS, NS>>>();                  // tab + twiddles
    {
        dim3 grid(NS / RROWS, NB);
        row_fft_kernel<<<grid, 256>>>(z, tt);
    }
    {
        dim3 grid(NT, NB, 2);
        col_fft_kernel<<<grid, 256>>>();
    }
    {
        dim3 grid(NB, 8);
        reduce1a_kernel<<<grid, 512>>>();
    }
    reduce1b_kernel<<<NB, 512>>>();
    reduce2_kernel<<<1, 1>>>(out);
}